// round 14
// baseline (speedup 1.0000x reference)
#include <cuda_runtime.h>
#include <cuda_fp16.h>
#include <mma.h>
#include <cstdint>

using namespace nvcuda;

#define T_TOK 4096
#define D_DIM 768
#define H_DIM 2688
#define E_NUM 8
#define BK 32

// ---------------- scratch (static device globals; no allocations) ----------------
__device__ float g_z_acc;
__device__ int   g_cnt[E_NUM];
__device__ int   g_tok[E_NUM * T_TOK];
__device__ int   g_slot[2 * T_TOK];   // per token: two (expert*T_TOK + pos) slots
__device__ float g_wt [2 * T_TOK];    // per token: two softmax weights
// fp16 copies (RN)
__device__ __half g_xh [(size_t)T_TOK * D_DIM];
__device__ __half g_wgh[(size_t)E_NUM * D_DIM * H_DIM];
__device__ __half g_wuh[(size_t)E_NUM * D_DIM * H_DIM];
__device__ __half g_wdh[(size_t)E_NUM * H_DIM * D_DIM];
// act scratch: [E*T, H] fp16
__device__ __half g_acth[(size_t)E_NUM * T_TOK * H_DIM];
// per-slot down-proj result: [E*T, D] fp32
__device__ float g_y[(size_t)E_NUM * T_TOK * D_DIM];

__device__ __forceinline__ uint32_t smem_u32(const void* p) {
    return (uint32_t)__cvta_generic_to_shared(p);
}
__device__ __forceinline__ void cpa16(uint32_t s, const void* g) {
    asm volatile("cp.async.cg.shared.global [%0], [%1], 16;" :: "r"(s), "l"(g));
}
#define CP_COMMIT() asm volatile("cp.async.commit_group;" ::: "memory")
#define CP_WAIT2()  asm volatile("cp.async.wait_group 2;" ::: "memory")
#define CP_WAIT1()  asm volatile("cp.async.wait_group 1;" ::: "memory")

// ---------------- kernel 0: init counters ----------------
__global__ void k_init() {
    if (threadIdx.x < E_NUM) g_cnt[threadIdx.x] = 0;
    if (threadIdx.x == 31)   g_z_acc = 0.0f;
}

// ---------------- kernel 0b: fp32 -> fp16 copies ----------------
__global__ void k_cvt(const float* __restrict__ x,
                      const float* __restrict__ wg,
                      const float* __restrict__ wu,
                      const float* __restrict__ wd) {
    const size_t i0 = (size_t)blockIdx.x * blockDim.x + threadIdx.x;
    const size_t st = (size_t)gridDim.x * blockDim.x;
    const size_t NX = (size_t)T_TOK * D_DIM / 4;
    const size_t NW = (size_t)E_NUM * D_DIM * H_DIM / 4;
    for (size_t i = i0; i < NX; i += st) {
        float4 v = ((const float4*)x)[i];
        ((__half2*)g_xh)[2 * i]     = __floats2half2_rn(v.x, v.y);
        ((__half2*)g_xh)[2 * i + 1] = __floats2half2_rn(v.z, v.w);
    }
    for (size_t i = i0; i < NW; i += st) {
        float4 v = ((const float4*)wg)[i];
        ((__half2*)g_wgh)[2 * i]     = __floats2half2_rn(v.x, v.y);
        ((__half2*)g_wgh)[2 * i + 1] = __floats2half2_rn(v.z, v.w);
    }
    for (size_t i = i0; i < NW; i += st) {
        float4 v = ((const float4*)wu)[i];
        ((__half2*)g_wuh)[2 * i]     = __floats2half2_rn(v.x, v.y);
        ((__half2*)g_wuh)[2 * i + 1] = __floats2half2_rn(v.z, v.w);
    }
    for (size_t i = i0; i < NW; i += st) {
        float4 v = ((const float4*)wd)[i];
        ((__half2*)g_wdh)[2 * i]     = __floats2half2_rn(v.x, v.y);
        ((__half2*)g_wdh)[2 * i + 1] = __floats2half2_rn(v.z, v.w);
    }
}

// ---------------- kernel 1: router ----------------
__global__ void k_router(const float* __restrict__ x,
                         const float* __restrict__ gw,
                         const float* __restrict__ bias) {
    int gwarp = (blockIdx.x * blockDim.x + threadIdx.x) >> 5;
    int lane  = threadIdx.x & 31;
    if (gwarp >= T_TOK) return;
    const float* xr = x + (size_t)gwarp * D_DIM;

    float xv[24];
#pragma unroll
    for (int i = 0; i < 24; i++) xv[i] = xr[i * 32 + lane];

    float lg[8];
#pragma unroll
    for (int e = 0; e < 8; e++) {
        const float* w = gw + e * D_DIM;
        float s = 0.0f;
#pragma unroll
        for (int i = 0; i < 24; i++) s += xv[i] * w[i * 32 + lane];
#pragma unroll
        for (int o = 16; o > 0; o >>= 1) s += __shfl_xor_sync(0xffffffffu, s, o);
        lg[e] = s;
    }

    if (lane == 0) {
        float b1 = -1e30f, b2 = -1e30f; int i1 = 0, i2 = 0;
#pragma unroll
        for (int e = 0; e < 8; e++) {
            float b = lg[e] + bias[e];
            if (b > b1)      { b2 = b1; i2 = i1; b1 = b; i1 = e; }
            else if (b > b2) { b2 = b;  i2 = e; }
        }
        float l1 = lg[i1], l2 = lg[i2];
        float m = fmaxf(l1, l2);
        float e1 = expf(l1 - m), e2 = expf(l2 - m);
        float inv = 1.0f / (e1 + e2);
        float w1 = e1 * inv, w2 = e2 * inv;

        float mm = lg[0];
#pragma unroll
        for (int e = 1; e < 8; e++) mm = fmaxf(mm, lg[e]);
        float s = 0.0f;
#pragma unroll
        for (int e = 0; e < 8; e++) s += expf(lg[e] - mm);
        float lse = mm + logf(s);
        atomicAdd(&g_z_acc, lse * lse);

        int p1 = atomicAdd(&g_cnt[i1], 1);
        g_tok[i1 * T_TOK + p1] = gwarp;
        g_slot[2 * gwarp + 0] = i1 * T_TOK + p1;
        g_wt  [2 * gwarp + 0] = w1;
        int p2 = atomicAdd(&g_cnt[i2], 1);
        g_tok[i2 * T_TOK + p2] = gwarp;
        g_slot[2 * gwarp + 1] = i2 * T_TOK + p2;
        g_wt  [2 * gwarp + 1] = w2;
    }
}

// smem layout constants (in halves)
#define G1_A_ST   (128 * 40)
#define G1_B_ST   (32 * 72)
#define G1_STAGES 4
#define G1_SMEM   ((G1_A_ST + 2 * G1_B_ST) * G1_STAGES * 2)   // 77824 B

#define G2_A_ST   (128 * 40)
#define G2_B_ST   (32 * 136)
#define G2_STAGES 3
#define G2_SMEM   ((G2_A_ST + G2_B_ST) * G2_STAGES * 2)       // 56832 B

// ---------------- kernel 2: fp16 GEMM1, 128x(64+64), 4 warps, warp=64x32 dual ----------------
__global__ void __launch_bounds__(128, 2) k_gemm1() {
    extern __shared__ __align__(16) char dynsm[];
    const int e   = blockIdx.z;
    const int cnt = g_cnt[e];
    const int m0  = blockIdx.x * 128;
    if (m0 >= cnt) return;
    const int n0  = blockIdx.y * 64;

    __half* sA  = (__half*)dynsm;                       // [4][128][40]
    __half* sBg = sA + G1_STAGES * G1_A_ST;             // [4][32][72]
    __half* sBu = sBg + G1_STAGES * G1_B_ST;            // [4][32][72]

    const int tid  = threadIdx.x;
    const int warp = tid >> 5;
    const int wm   = warp >> 1;   // 0..1 -> 64-row slab
    const int wn   = warp & 1;    // 0..1 -> 32-col slab

    // A staging: 128 rows x 32 halves -> 512 x 16B chunks, 4/thread
    const __half* a_src[4];
    uint32_t a_dst[4];
#pragma unroll
    for (int q = 0; q < 4; q++) {
        int ch = q * 128 + tid;
        int r = ch >> 2, c = (ch & 3) * 8;
        int row = m0 + r;
        int tok = g_tok[e * T_TOK + (row < cnt ? row : cnt - 1)];
        a_src[q] = g_xh + (size_t)tok * D_DIM + c;
        a_dst[q] = smem_u32(sA + r * 40 + c);
    }
    // B staging: 32 rows x 64 halves -> 256 chunks, 2/thread per matrix
    const __half* bg_src[2]; const __half* bu_src[2];
    uint32_t bg_dst[2], bu_dst[2];
    const size_t wb = (size_t)e * D_DIM * H_DIM;
#pragma unroll
    for (int q = 0; q < 2; q++) {
        int ch = q * 128 + tid;
        int r = ch >> 3, c = (ch & 7) * 8;
        size_t o = wb + (size_t)r * H_DIM + n0 + c;
        bg_src[q] = g_wgh + o;
        bu_src[q] = g_wuh + o;
        bg_dst[q] = smem_u32(sBg + r * 72 + c);
        bu_dst[q] = smem_u32(sBu + r * 72 + c);
    }

    wmma::fragment<wmma::accumulator, 16, 16, 16, float> accg[4][2], accu[4][2];
#pragma unroll
    for (int i = 0; i < 4; i++)
#pragma unroll
        for (int j = 0; j < 2; j++) {
            wmma::fill_fragment(accg[i][j], 0.0f);
            wmma::fill_fragment(accu[i][j], 0.0f);
        }

    auto issue = [&](int s, int kt) {
        const int k0 = kt * BK;
        const uint32_t aOfs = s * (G1_A_ST * 2);
        const uint32_t bOfs = s * (G1_B_ST * 2);
#pragma unroll
        for (int q = 0; q < 4; q++)
            cpa16(a_dst[q] + aOfs, a_src[q] + k0);
        const size_t o = (size_t)k0 * H_DIM;
#pragma unroll
        for (int q = 0; q < 2; q++) {
            cpa16(bg_dst[q] + bOfs, bg_src[q] + o);
            cpa16(bu_dst[q] + bOfs, bu_src[q] + o);
        }
    };

    const int NK = D_DIM / BK;   // 24
    issue(0, 0); CP_COMMIT();
    issue(1, 1); CP_COMMIT();
    issue(2, 2); CP_COMMIT();

    for (int kt = 0; kt < NK; kt++) {
        const int cur = kt & 3;
        CP_WAIT2();
        __syncthreads();
        if (kt + 3 < NK) issue((kt + 3) & 3, kt + 3);
        CP_COMMIT();
        const __half* cA  = sA  + cur * G1_A_ST;
        const __half* cBg = sBg + cur * G1_B_ST;
        const __half* cBu = sBu + cur * G1_B_ST;
#pragma unroll
        for (int kk = 0; kk < 2; kk++) {
            wmma::fragment<wmma::matrix_a, 16, 16, 16, __half, wmma::row_major> af[4];
            wmma::fragment<wmma::matrix_b, 16, 16, 16, __half, wmma::row_major> bgf[2], buf2[2];
#pragma unroll
            for (int i = 0; i < 4; i++)
                wmma::load_matrix_sync(af[i], cA + (wm * 64 + i * 16) * 40 + kk * 16, 40);
#pragma unroll
            for (int j = 0; j < 2; j++) {
                wmma::load_matrix_sync(bgf[j],  cBg + (kk * 16) * 72 + wn * 32 + j * 16, 72);
                wmma::load_matrix_sync(buf2[j], cBu + (kk * 16) * 72 + wn * 32 + j * 16, 72);
            }
#pragma unroll
            for (int i = 0; i < 4; i++)
#pragma unroll
                for (int j = 0; j < 2; j++) {
                    wmma::mma_sync(accg[i][j], af[i], bgf[j],  accg[i][j]);
                    wmma::mma_sync(accu[i][j], af[i], buf2[j], accu[i][j]);
                }
        }
    }

    // epilogue: act = silu(g)*u fragment-wise (accg/accu element-aligned), stage fp32 -> fp16
    __syncthreads();
    float* C = (float*)dynsm;   // [128][68]
#pragma unroll
    for (int i = 0; i < 4; i++)
#pragma unroll
        for (int j = 0; j < 2; j++) {
#pragma unroll
            for (int t = 0; t < accg[i][j].num_elements; t++) {
                float g = accg[i][j].x[t];
                float u = accu[i][j].x[t];
                float sg = 1.0f / (1.0f + expf(-g));
                accg[i][j].x[t] = g * sg * u;
            }
            wmma::store_matrix_sync(C + (wm * 64 + i * 16) * 68 + wn * 32 + j * 16,
                                    accg[i][j], 68, wmma::mem_row_major);
        }
    __syncthreads();
    // 128x64 -> half2: 4096 pairs, 32/thread (junk rows in-bounds, never read)
    for (int idx = tid; idx < 128 * 32; idx += 128) {
        int r = idx >> 5, c2 = (idx & 31) * 2;
        __half2 h = __floats2half2_rn(C[r * 68 + c2], C[r * 68 + c2 + 1]);
        *(__half2*)(g_acth + ((size_t)e * T_TOK + m0 + r) * H_DIM + n0 + c2) = h;
    }
}

// ---------------- kernel 3: fp16 GEMM2, 128x128, 4 warps, warp=64x64 ----------------
__global__ void __launch_bounds__(128, 2) k_gemm2() {
    extern __shared__ __align__(16) char dynsm[];
    const int e   = blockIdx.z;
    const int cnt = g_cnt[e];
    const int m0  = blockIdx.y * 128;
    if (m0 >= cnt) return;
    const int n0  = blockIdx.x * 128;

    __half* sA = (__half*)dynsm;               // [3][128][40]
    __half* sB = sA + G2_STAGES * G2_A_ST;     // [3][32][136]

    const int tid  = threadIdx.x;
    const int warp = tid >> 5;
    const int wm   = warp >> 1;   // 0..1 -> 64-row slab
    const int wn   = warp & 1;    // 0..1 -> 64-col slab

    // A: 512 chunks, 4/thread (fp16 act, dense slot rows)
    const __half* a_src[4];
    uint32_t a_dst[4];
#pragma unroll
    for (int q = 0; q < 4; q++) {
        int ch = q * 128 + tid;
        int r = ch >> 2, c = (ch & 3) * 8;
        a_src[q] = g_acth + ((size_t)e * T_TOK + m0 + r) * H_DIM + c;
        a_dst[q] = smem_u32(sA + r * 40 + c);
    }
    // B: 32 rows x 128 halves -> 512 chunks, 4/thread
    const __half* b_src[4];
    uint32_t b_dst[4];
    const size_t wb = (size_t)e * H_DIM * D_DIM;
#pragma unroll
    for (int q = 0; q < 4; q++) {
        int ch = q * 128 + tid;
        int r = ch >> 4, c = (ch & 15) * 8;
        b_src[q] = g_wdh + wb + (size_t)r * D_DIM + n0 + c;
        b_dst[q] = smem_u32(sB + r * 136 + c);
    }

    wmma::fragment<wmma::accumulator, 16, 16, 16, float> acc[4][4];
#pragma unroll
    for (int i = 0; i < 4; i++)
#pragma unroll
        for (int j = 0; j < 4; j++) wmma::fill_fragment(acc[i][j], 0.0f);

    auto issue = [&](int s, int kt) {
        const int k0 = kt * BK;
        const uint32_t aOfs = s * (G2_A_ST * 2);
        const uint32_t bOfs = s * (G2_B_ST * 2);
#pragma unroll
        for (int q = 0; q < 4; q++)
            cpa16(a_dst[q] + aOfs, a_src[q] + k0);
#pragma unroll
        for (int q = 0; q < 4; q++)
            cpa16(b_dst[q] + bOfs, b_src[q] + (size_t)k0 * D_DIM);
    };

    const int NK = H_DIM / BK;   // 84
    issue(0, 0); CP_COMMIT();
    issue(1, 1); CP_COMMIT();

    int cur = 0;
    for (int kt = 0; kt < NK; kt++) {
        CP_WAIT1();
        __syncthreads();
        if (kt + 2 < NK) issue((cur + 2) % 3, kt + 2);
        CP_COMMIT();
        const __half* cA = sA + cur * G2_A_ST;
        const __half* cB = sB + cur * G2_B_ST;
#pragma unroll
        for (int kk = 0; kk < 2; kk++) {
            wmma::fragment<wmma::matrix_a, 16, 16, 16, __half, wmma::row_major> af[4];
            wmma::fragment<wmma::matrix_b, 16, 16, 16, __half, wmma::row_major> bf[4];
#pragma unroll
            for (int i = 0; i < 4; i++)
                wmma::load_matrix_sync(af[i], cA + (wm * 64 + i * 16) * 40 + kk * 16, 40);
#pragma unroll
            for (int j = 0; j < 4; j++)
                wmma::load_matrix_sync(bf[j], cB + (kk * 16) * 136 + wn * 64 + j * 16, 136);
#pragma unroll
            for (int i = 0; i < 4; i++)
#pragma unroll
                for (int j = 0; j < 4; j++)
                    wmma::mma_sync(acc[i][j], af[i], bf[j], acc[i][j]);
        }
        cur = (cur + 1) % 3;
    }

    // epilogue: per-slot fp32 result direct to g_y (no atomics; junk rows never combined)
    float* ybase = g_y + ((size_t)e * T_TOK + m0) * D_DIM + n0;
#pragma unroll
    for (int i = 0; i < 4; i++)
#pragma unroll
        for (int j = 0; j < 4; j++)
            wmma::store_matrix_sync(ybase + (size_t)(wm * 64 + i * 16) * D_DIM + wn * 64 + j * 16,
                                    acc[i][j], D_DIM, wmma::mem_row_major);
}

// ---------------- kernel 4: combine two expert slots per token ----------------
__global__ void k_combine(float* __restrict__ out) {
    const int t = blockIdx.x;
    const int s0 = g_slot[2 * t], s1 = g_slot[2 * t + 1];
    const float w0 = g_wt[2 * t], w1 = g_wt[2 * t + 1];
    const float4* y0 = (const float4*)(g_y + (size_t)s0 * D_DIM);
    const float4* y1 = (const float4*)(g_y + (size_t)s1 * D_DIM);
    float4 a = y0[threadIdx.x];
    float4 b = y1[threadIdx.x];
    float4 r;
    r.x = w0 * a.x + w1 * b.x;
    r.y = w0 * a.y + w1 * b.y;
    r.z = w0 * a.z + w1 * b.z;
    r.w = w0 * a.w + w1 * b.w;
    ((float4*)(out + (size_t)t * D_DIM))[threadIdx.x] = r;
}

// ---------------- kernel 5: finalize z-loss ----------------
__global__ void k_final(float* __restrict__ out, int out_size) {
    if (out_size > T_TOK * D_DIM)
        out[T_TOK * D_DIM] = 1e-5f * g_z_acc / (float)T_TOK;
}

// ---------------- launcher ----------------
extern "C" void kernel_launch(void* const* d_in, const int* in_sizes, int n_in,
                              void* d_out, int out_size) {
    const float* x     = (const float*)d_in[0];  // [2,2048,768]
    const float* gw    = (const float*)d_in[1];  // [8,768]
    const float* bias  = (const float*)d_in[2];  // [8]
    const float* wgate = (const float*)d_in[3];  // [8,768,2688]
    const float* wup   = (const float*)d_in[4];  // [8,768,2688]
    const float* wdown = (const float*)d_in[5];  // [8,2688,768]
    float* out = (float*)d_out;

    static bool attr_set = false;
    if (!attr_set) {
        cudaFuncSetAttribute(k_gemm1, cudaFuncAttributeMaxDynamicSharedMemorySize, G1_SMEM);
        cudaFuncSetAttribute(k_gemm2, cudaFuncAttributeMaxDynamicSharedMemorySize, G2_SMEM);
        attr_set = true;
    }

    k_init<<<1, 32>>>();
    k_cvt<<<2048, 256>>>(x, wgate, wup, wdown);
    k_router<<<T_TOK / 8, 256>>>(x, gw, bias);

    dim3 g1(T_TOK / 128, H_DIM / 64, E_NUM);   // 32 x 42 x 8 (M fastest -> weight-slab L2 reuse)
    k_gemm1<<<g1, 128, G1_SMEM>>>();

    dim3 g2(D_DIM / 128, T_TOK / 128, E_NUM);  // 6 x 32 x 8 (N fastest -> A-slab L2 reuse)
    k_gemm2<<<g2, 128, G2_SMEM>>>();

    k_combine<<<T_TOK, 192>>>(out);
    k_final<<<1, 1>>>(out, out_size);
}

// round 15
// speedup vs baseline: 1.0557x; 1.0557x over previous
#include <cuda_runtime.h>
#include <cuda_fp16.h>
#include <mma.h>
#include <cstdint>

using namespace nvcuda;

#define T_TOK 4096
#define D_DIM 768
#define H_DIM 2688
#define E_NUM 8

// ---------------- scratch (static device globals; no allocations) ----------------
__device__ float g_z_acc;
__device__ int   g_cnt[E_NUM];
__device__ int   g_tok[E_NUM * T_TOK];
__device__ int   g_slot[2 * T_TOK];   // per token: two (expert*T_TOK + pos) slots
__device__ float g_wt [2 * T_TOK];    // per token: two softmax weights
// fp16 copies (RN)
__device__ __half g_xh [(size_t)T_TOK * D_DIM];
__device__ __half g_wgh[(size_t)E_NUM * D_DIM * H_DIM];
__device__ __half g_wuh[(size_t)E_NUM * D_DIM * H_DIM];
__device__ __half g_wdh[(size_t)E_NUM * H_DIM * D_DIM];
// act scratch: [E*T, H] fp16
__device__ __half g_acth[(size_t)E_NUM * T_TOK * H_DIM];
// per-slot down-proj result: [E*T, D] fp32
__device__ float g_y[(size_t)E_NUM * T_TOK * D_DIM];

__device__ __forceinline__ uint32_t smem_u32(const void* p) {
    return (uint32_t)__cvta_generic_to_shared(p);
}
__device__ __forceinline__ void cpa16(uint32_t s, const void* g) {
    asm volatile("cp.async.cg.shared.global [%0], [%1], 16;" :: "r"(s), "l"(g));
}
#define CP_COMMIT() asm volatile("cp.async.commit_group;" ::: "memory")
#define CP_WAIT1()  asm volatile("cp.async.wait_group 1;" ::: "memory")

// ---------------- kernel 0: init counters ----------------
__global__ void k_init() {
    if (threadIdx.x < E_NUM) g_cnt[threadIdx.x] = 0;
    if (threadIdx.x == 31)   g_z_acc = 0.0f;
}

// ---------------- kernel 0b: fp32 -> fp16 copies ----------------
__global__ void k_cvt(const float* __restrict__ x,
                      const float* __restrict__ wg,
                      const float* __restrict__ wu,
                      const float* __restrict__ wd) {
    const size_t i0 = (size_t)blockIdx.x * blockDim.x + threadIdx.x;
    const size_t st = (size_t)gridDim.x * blockDim.x;
    const size_t NX = (size_t)T_TOK * D_DIM / 4;
    const size_t NW = (size_t)E_NUM * D_DIM * H_DIM / 4;
    for (size_t i = i0; i < NX; i += st) {
        float4 v = ((const float4*)x)[i];
        ((__half2*)g_xh)[2 * i]     = __floats2half2_rn(v.x, v.y);
        ((__half2*)g_xh)[2 * i + 1] = __floats2half2_rn(v.z, v.w);
    }
    for (size_t i = i0; i < NW; i += st) {
        float4 v = ((const float4*)wg)[i];
        ((__half2*)g_wgh)[2 * i]     = __floats2half2_rn(v.x, v.y);
        ((__half2*)g_wgh)[2 * i + 1] = __floats2half2_rn(v.z, v.w);
    }
    for (size_t i = i0; i < NW; i += st) {
        float4 v = ((const float4*)wu)[i];
        ((__half2*)g_wuh)[2 * i]     = __floats2half2_rn(v.x, v.y);
        ((__half2*)g_wuh)[2 * i + 1] = __floats2half2_rn(v.z, v.w);
    }
    for (size_t i = i0; i < NW; i += st) {
        float4 v = ((const float4*)wd)[i];
        ((__half2*)g_wdh)[2 * i]     = __floats2half2_rn(v.x, v.y);
        ((__half2*)g_wdh)[2 * i + 1] = __floats2half2_rn(v.z, v.w);
    }
}

// ---------------- kernel 1: router ----------------
__global__ void k_router(const float* __restrict__ x,
                         const float* __restrict__ gw,
                         const float* __restrict__ bias) {
    int gwarp = (blockIdx.x * blockDim.x + threadIdx.x) >> 5;
    int lane  = threadIdx.x & 31;
    if (gwarp >= T_TOK) return;
    const float* xr = x + (size_t)gwarp * D_DIM;

    float xv[24];
#pragma unroll
    for (int i = 0; i < 24; i++) xv[i] = xr[i * 32 + lane];

    float lg[8];
#pragma unroll
    for (int e = 0; e < 8; e++) {
        const float* w = gw + e * D_DIM;
        float s = 0.0f;
#pragma unroll
        for (int i = 0; i < 24; i++) s += xv[i] * w[i * 32 + lane];
#pragma unroll
        for (int o = 16; o > 0; o >>= 1) s += __shfl_xor_sync(0xffffffffu, s, o);
        lg[e] = s;
    }

    if (lane == 0) {
        float b1 = -1e30f, b2 = -1e30f; int i1 = 0, i2 = 0;
#pragma unroll
        for (int e = 0; e < 8; e++) {
            float b = lg[e] + bias[e];
            if (b > b1)      { b2 = b1; i2 = i1; b1 = b; i1 = e; }
            else if (b > b2) { b2 = b;  i2 = e; }
        }
        float l1 = lg[i1], l2 = lg[i2];
        float m = fmaxf(l1, l2);
        float e1 = expf(l1 - m), e2 = expf(l2 - m);
        float inv = 1.0f / (e1 + e2);
        float w1 = e1 * inv, w2 = e2 * inv;

        float mm = lg[0];
#pragma unroll
        for (int e = 1; e < 8; e++) mm = fmaxf(mm, lg[e]);
        float s = 0.0f;
#pragma unroll
        for (int e = 0; e < 8; e++) s += expf(lg[e] - mm);
        float lse = mm + logf(s);
        atomicAdd(&g_z_acc, lse * lse);

        int p1 = atomicAdd(&g_cnt[i1], 1);
        g_tok[i1 * T_TOK + p1] = gwarp;
        g_slot[2 * gwarp + 0] = i1 * T_TOK + p1;
        g_wt  [2 * gwarp + 0] = w1;
        int p2 = atomicAdd(&g_cnt[i2], 1);
        g_tok[i2 * T_TOK + p2] = gwarp;
        g_slot[2 * gwarp + 1] = i2 * T_TOK + p2;
        g_wt  [2 * gwarp + 1] = w2;
    }
}

// smem layout constants (in halves); BK=64, 3 stages, 1 sync per 64-K step
#define G1_A_ST   (128 * 72)
#define G1_B_ST   (64 * 72)
#define G1_SMEM   ((G1_A_ST + 2 * G1_B_ST) * 3 * 2)   // 110592 B

#define G2_A_ST   (128 * 72)
#define G2_B_ST   (64 * 136)
#define G2_SMEM   ((G2_A_ST + G2_B_ST) * 3 * 2)       // 107520 B

// ---------------- kernel 2: fp16 GEMM1, 128x64 tile, BK=64, 3-stage ----------------
// g = X*Wg, u = X*Wu (shared A), act = silu(g)*u -> g_acth (fp16)
__global__ void __launch_bounds__(256, 2) k_gemm1() {
    extern __shared__ __align__(16) char dynsm[];
    const int e   = blockIdx.z;
    const int cnt = g_cnt[e];
    const int m0  = blockIdx.x * 128;
    if (m0 >= cnt) return;
    const int n0  = blockIdx.y * 64;

    __half* sA  = (__half*)dynsm;                 // [3][128][72]
    __half* sBg = sA + 3 * G1_A_ST;               // [3][64][72]
    __half* sBu = sBg + 3 * G1_B_ST;              // [3][64][72]

    const int tid  = threadIdx.x;
    const int warp = tid >> 5;
    const int wm   = warp >> 1;   // 0..3 -> 32-row slab
    const int wn   = warp & 1;    // 0..1 -> 32-col slab

    // A staging: 128 rows x 64 halves -> 1024 x 16B chunks, 4/thread
    const __half* a_src[4];
    uint32_t a_dst[4];
#pragma unroll
    for (int q = 0; q < 4; q++) {
        int ch = q * 256 + tid;
        int r = ch >> 3, c = (ch & 7) * 8;
        int row = m0 + r;
        int tok = g_tok[e * T_TOK + (row < cnt ? row : cnt - 1)];
        a_src[q] = g_xh + (size_t)tok * D_DIM + c;
        a_dst[q] = smem_u32(sA + r * 72 + c);
    }
    // B staging: 64 rows x 64 halves -> 512 chunks, 2/thread per matrix
    const __half* bg_src[2]; const __half* bu_src[2];
    uint32_t bg_dst[2], bu_dst[2];
    const size_t wb = (size_t)e * D_DIM * H_DIM;
#pragma unroll
    for (int q = 0; q < 2; q++) {
        int ch = q * 256 + tid;
        int r = ch >> 3, c = (ch & 7) * 8;
        size_t o = wb + (size_t)r * H_DIM + n0 + c;
        bg_src[q] = g_wgh + o;
        bu_src[q] = g_wuh + o;
        bg_dst[q] = smem_u32(sBg + r * 72 + c);
        bu_dst[q] = smem_u32(sBu + r * 72 + c);
    }

    wmma::fragment<wmma::accumulator, 16, 16, 16, float> accg[2][2], accu[2][2];
#pragma unroll
    for (int i = 0; i < 2; i++)
#pragma unroll
        for (int j = 0; j < 2; j++) {
            wmma::fill_fragment(accg[i][j], 0.0f);
            wmma::fill_fragment(accu[i][j], 0.0f);
        }

    auto issue = [&](int s, int kt) {
        const int k0 = kt * 64;
        const uint32_t aOfs = s * (G1_A_ST * 2);
        const uint32_t bOfs = s * (G1_B_ST * 2);
#pragma unroll
        for (int q = 0; q < 4; q++)
            cpa16(a_dst[q] + aOfs, a_src[q] + k0);
        const size_t o = (size_t)k0 * H_DIM;
#pragma unroll
        for (int q = 0; q < 2; q++) {
            cpa16(bg_dst[q] + bOfs, bg_src[q] + o);
            cpa16(bu_dst[q] + bOfs, bu_src[q] + o);
        }
    };

    const int NK = D_DIM / 64;   // 12
    issue(0, 0); CP_COMMIT();
    issue(1, 1); CP_COMMIT();

    int cur = 0;
    for (int kt = 0; kt < NK; kt++) {
        CP_WAIT1();
        __syncthreads();
        if (kt + 2 < NK) issue((cur + 2) % 3, kt + 2);
        CP_COMMIT();
        const __half* cA  = sA  + cur * G1_A_ST;
        const __half* cBg = sBg + cur * G1_B_ST;
        const __half* cBu = sBu + cur * G1_B_ST;
#pragma unroll
        for (int kk = 0; kk < 4; kk++) {
            wmma::fragment<wmma::matrix_a, 16, 16, 16, __half, wmma::row_major> af[2];
            wmma::fragment<wmma::matrix_b, 16, 16, 16, __half, wmma::row_major> bgf[2], buf2[2];
#pragma unroll
            for (int i = 0; i < 2; i++)
                wmma::load_matrix_sync(af[i], cA + (wm * 32 + i * 16) * 72 + kk * 16, 72);
#pragma unroll
            for (int j = 0; j < 2; j++) {
                wmma::load_matrix_sync(bgf[j],  cBg + (kk * 16) * 72 + wn * 32 + j * 16, 72);
                wmma::load_matrix_sync(buf2[j], cBu + (kk * 16) * 72 + wn * 32 + j * 16, 72);
            }
#pragma unroll
            for (int i = 0; i < 2; i++)
#pragma unroll
                for (int j = 0; j < 2; j++) {
                    wmma::mma_sync(accg[i][j], af[i], bgf[j],  accg[i][j]);
                    wmma::mma_sync(accu[i][j], af[i], buf2[j], accu[i][j]);
                }
        }
        cur = (cur + 1) % 3;
    }

    // epilogue: act = silu(g)*u (fp32 math) -> fp16 g_acth, staged via dynsm as float C[128][68]
    __syncthreads();
    float* C = (float*)dynsm;
#pragma unroll
    for (int i = 0; i < 2; i++)
#pragma unroll
        for (int j = 0; j < 2; j++) {
#pragma unroll
            for (int t = 0; t < accg[i][j].num_elements; t++) {
                float g = accg[i][j].x[t];
                float u = accu[i][j].x[t];
                float sg = 1.0f / (1.0f + expf(-g));
                accg[i][j].x[t] = g * sg * u;
            }
            wmma::store_matrix_sync(C + (wm * 32 + i * 16) * 68 + wn * 32 + j * 16,
                                    accg[i][j], 68, wmma::mem_row_major);
        }
    __syncthreads();
    // 128x64 elems -> half2: 4096 pairs, 16/thread (junk rows in-bounds, never read)
    for (int idx = tid; idx < 128 * 32; idx += 256) {
        int r = idx >> 5, c2 = (idx & 31) * 2;
        __half2 h = __floats2half2_rn(C[r * 68 + c2], C[r * 68 + c2 + 1]);
        *(__half2*)(g_acth + ((size_t)e * T_TOK + m0 + r) * H_DIM + n0 + c2) = h;
    }
}

// ---------------- kernel 3: fp16 GEMM2, 128x128 tile, BK=64, 3-stage ----------------
__global__ void __launch_bounds__(256, 2) k_gemm2() {
    extern __shared__ __align__(16) char dynsm[];
    const int e   = blockIdx.z;
    const int cnt = g_cnt[e];
    const int m0  = blockIdx.y * 128;
    if (m0 >= cnt) return;
    const int n0  = blockIdx.x * 128;

    __half* sA = (__half*)dynsm;             // [3][128][72]
    __half* sB = sA + 3 * G2_A_ST;           // [3][64][136]

    const int tid  = threadIdx.x;
    const int warp = tid >> 5;
    const int wm   = warp >> 1;   // 0..3 -> 32-row slab
    const int wn   = warp & 1;    // 0..1 -> 64-col slab

    // A: 128 rows x 64 halves -> 1024 chunks, 4/thread (fp16 act, dense slot rows)
    const __half* a_src[4];
    uint32_t a_dst[4];
#pragma unroll
    for (int q = 0; q < 4; q++) {
        int ch = q * 256 + tid;
        int r = ch >> 3, c = (ch & 7) * 8;
        a_src[q] = g_acth + ((size_t)e * T_TOK + m0 + r) * H_DIM + c;
        a_dst[q] = smem_u32(sA + r * 72 + c);
    }
    // B: 64 rows x 128 halves -> 1024 chunks, 4/thread
    const __half* b_src[4];
    uint32_t b_dst[4];
    const size_t wb = (size_t)e * H_DIM * D_DIM;
#pragma unroll
    for (int q = 0; q < 4; q++) {
        int ch = q * 256 + tid;
        int r = ch >> 4, c = (ch & 15) * 8;
        b_src[q] = g_wdh + wb + (size_t)r * D_DIM + n0 + c;
        b_dst[q] = smem_u32(sB + r * 136 + c);
    }

    wmma::fragment<wmma::accumulator, 16, 16, 16, float> acc[2][4];
#pragma unroll
    for (int i = 0; i < 2; i++)
#pragma unroll
        for (int j = 0; j < 4; j++) wmma::fill_fragment(acc[i][j], 0.0f);

    auto issue = [&](int s, int kt) {
        const int k0 = kt * 64;
        const uint32_t aOfs = s * (G2_A_ST * 2);
        const uint32_t bOfs = s * (G2_B_ST * 2);
#pragma unroll
        for (int q = 0; q < 4; q++)
            cpa16(a_dst[q] + aOfs, a_src[q] + k0);
#pragma unroll
        for (int q = 0; q < 4; q++)
            cpa16(b_dst[q] + bOfs, b_src[q] + (size_t)k0 * D_DIM);
    };

    const int NK = H_DIM / 64;   // 42
    issue(0, 0); CP_COMMIT();
    issue(1, 1); CP_COMMIT();

    int cur = 0;
    for (int kt = 0; kt < NK; kt++) {
        CP_WAIT1();
        __syncthreads();
        if (kt + 2 < NK) issue((cur + 2) % 3, kt + 2);
        CP_COMMIT();
        const __half* cA = sA + cur * G2_A_ST;
        const __half* cB = sB + cur * G2_B_ST;
#pragma unroll
        for (int kk = 0; kk < 4; kk++) {
            wmma::fragment<wmma::matrix_a, 16, 16, 16, __half, wmma::row_major> af[2];
            wmma::fragment<wmma::matrix_b, 16, 16, 16, __half, wmma::row_major> bf[4];
#pragma unroll
            for (int i = 0; i < 2; i++)
                wmma::load_matrix_sync(af[i], cA + (wm * 32 + i * 16) * 72 + kk * 16, 72);
#pragma unroll
            for (int j = 0; j < 4; j++)
                wmma::load_matrix_sync(bf[j], cB + (kk * 16) * 136 + wn * 64 + j * 16, 136);
#pragma unroll
            for (int i = 0; i < 2; i++)
#pragma unroll
                for (int j = 0; j < 4; j++)
                    wmma::mma_sync(acc[i][j], af[i], bf[j], acc[i][j]);
        }
        cur = (cur + 1) % 3;
    }

    // epilogue: per-slot fp32 result direct to g_y (no atomics; junk rows never combined)
    float* ybase = g_y + ((size_t)e * T_TOK + m0) * D_DIM + n0;
#pragma unroll
    for (int i = 0; i < 2; i++)
#pragma unroll
        for (int j = 0; j < 4; j++)
            wmma::store_matrix_sync(ybase + (size_t)(wm * 32 + i * 16) * D_DIM + wn * 64 + j * 16,
                                    acc[i][j], D_DIM, wmma::mem_row_major);
}

// ---------------- kernel 4: combine two expert slots per token ----------------
__global__ void k_combine(float* __restrict__ out) {
    const int t = blockIdx.x;
    const int s0 = g_slot[2 * t], s1 = g_slot[2 * t + 1];
    const float w0 = g_wt[2 * t], w1 = g_wt[2 * t + 1];
    const float4* y0 = (const float4*)(g_y + (size_t)s0 * D_DIM);
    const float4* y1 = (const float4*)(g_y + (size_t)s1 * D_DIM);
    float4 a = y0[threadIdx.x];
    float4 b = y1[threadIdx.x];
    float4 r;
    r.x = w0 * a.x + w1 * b.x;
    r.y = w0 * a.y + w1 * b.y;
    r.z = w0 * a.z + w1 * b.z;
    r.w = w0 * a.w + w1 * b.w;
    ((float4*)(out + (size_t)t * D_DIM))[threadIdx.x] = r;
}

// ---------------- kernel 5: finalize z-loss ----------------
__global__ void k_final(float* __restrict__ out, int out_size) {
    if (out_size > T_TOK * D_DIM)
        out[T_TOK * D_DIM] = 1e-5f * g_z_acc / (float)T_TOK;
}

// ---------------- launcher ----------------
extern "C" void kernel_launch(void* const* d_in, const int* in_sizes, int n_in,
                              void* d_out, int out_size) {
    const float* x     = (const float*)d_in[0];  // [2,2048,768]
    const float* gw    = (const float*)d_in[1];  // [8,768]
    const float* bias  = (const float*)d_in[2];  // [8]
    const float* wgate = (const float*)d_in[3];  // [8,768,2688]
    const float* wup   = (const float*)d_in[4];  // [8,768,2688]
    const float* wdown = (const float*)d_in[5];  // [8,2688,768]
    float* out = (float*)d_out;

    static bool attr_set = false;
    if (!attr_set) {
        cudaFuncSetAttribute(k_gemm1, cudaFuncAttributeMaxDynamicSharedMemorySize, G1_SMEM);
        cudaFuncSetAttribute(k_gemm2, cudaFuncAttributeMaxDynamicSharedMemorySize, G2_SMEM);
        attr_set = true;
    }

    k_init<<<1, 32>>>();
    k_cvt<<<2048, 256>>>(x, wgate, wup, wdown);
    k_router<<<T_TOK / 8, 256>>>(x, gw, bias);

    dim3 g1(T_TOK / 128, H_DIM / 64, E_NUM);   // 32 x 42 x 8 (M fastest -> weight-slab L2 reuse)
    k_gemm1<<<g1, 256, G1_SMEM>>>();

    dim3 g2(D_DIM / 128, T_TOK / 128, E_NUM);  // 6 x 32 x 8 (N fastest -> A-slab L2 reuse)
    k_gemm2<<<g2, 256, G2_SMEM>>>();

    k_combine<<<T_TOK, 192>>>(out);
    k_final<<<1, 1>>>(out, out_size);
}

// round 16
// speedup vs baseline: 1.5674x; 1.4847x over previous
#include <cuda_runtime.h>
#include <cuda_fp16.h>
#include <mma.h>
#include <cstdint>

using namespace nvcuda;

#define T_TOK 4096
#define D_DIM 768
#define H_DIM 2688
#define E_NUM 8
#define BK 32

// ---------------- scratch (static device globals; no allocations) ----------------
__device__ float g_z_acc;
__device__ int   g_cnt[E_NUM];
__device__ int   g_tok[E_NUM * T_TOK];
__device__ int   g_slot[2 * T_TOK];   // per token: two (expert*T_TOK + pos) slots
__device__ float g_wt [2 * T_TOK];    // per token: two softmax weights
// fp16 copies (RN)
__device__ __half g_xh [(size_t)T_TOK * D_DIM];
__device__ __half g_wgh[(size_t)E_NUM * D_DIM * H_DIM];
__device__ __half g_wuh[(size_t)E_NUM * D_DIM * H_DIM];
__device__ __half g_wdh[(size_t)E_NUM * H_DIM * D_DIM];
// act scratch: [E*T, H] fp16
__device__ __half g_acth[(size_t)E_NUM * T_TOK * H_DIM];
// per-slot down-proj result: [E*T, D] fp32
__device__ float g_y[(size_t)E_NUM * T_TOK * D_DIM];

__device__ __forceinline__ uint32_t smem_u32(const void* p) {
    return (uint32_t)__cvta_generic_to_shared(p);
}
__device__ __forceinline__ void cpa16(uint32_t s, const void* g) {
    asm volatile("cp.async.cg.shared.global [%0], [%1], 16;" :: "r"(s), "l"(g));
}
#define CP_COMMIT() asm volatile("cp.async.commit_group;" ::: "memory")
#define CP_WAIT2()  asm volatile("cp.async.wait_group 2;" ::: "memory")
#define CP_WAIT1()  asm volatile("cp.async.wait_group 1;" ::: "memory")

// ---------------- kernel 0: init counters ----------------
__global__ void k_init() {
    if (threadIdx.x < E_NUM) g_cnt[threadIdx.x] = 0;
    if (threadIdx.x == 31)   g_z_acc = 0.0f;
}

// ---------------- kernel 0b: fp32 -> fp16 copies ----------------
__global__ void k_cvt(const float* __restrict__ x,
                      const float* __restrict__ wg,
                      const float* __restrict__ wu,
                      const float* __restrict__ wd) {
    const size_t i0 = (size_t)blockIdx.x * blockDim.x + threadIdx.x;
    const size_t st = (size_t)gridDim.x * blockDim.x;
    const size_t NX = (size_t)T_TOK * D_DIM / 4;
    const size_t NW = (size_t)E_NUM * D_DIM * H_DIM / 4;
    for (size_t i = i0; i < NX; i += st) {
        float4 v = ((const float4*)x)[i];
        ((__half2*)g_xh)[2 * i]     = __floats2half2_rn(v.x, v.y);
        ((__half2*)g_xh)[2 * i + 1] = __floats2half2_rn(v.z, v.w);
    }
    for (size_t i = i0; i < NW; i += st) {
        float4 v = ((const float4*)wg)[i];
        ((__half2*)g_wgh)[2 * i]     = __floats2half2_rn(v.x, v.y);
        ((__half2*)g_wgh)[2 * i + 1] = __floats2half2_rn(v.z, v.w);
    }
    for (size_t i = i0; i < NW; i += st) {
        float4 v = ((const float4*)wu)[i];
        ((__half2*)g_wuh)[2 * i]     = __floats2half2_rn(v.x, v.y);
        ((__half2*)g_wuh)[2 * i + 1] = __floats2half2_rn(v.z, v.w);
    }
    for (size_t i = i0; i < NW; i += st) {
        float4 v = ((const float4*)wd)[i];
        ((__half2*)g_wdh)[2 * i]     = __floats2half2_rn(v.x, v.y);
        ((__half2*)g_wdh)[2 * i + 1] = __floats2half2_rn(v.z, v.w);
    }
}

// ---------------- kernel 1: router ----------------
__global__ void k_router(const float* __restrict__ x,
                         const float* __restrict__ gw,
                         const float* __restrict__ bias) {
    int gwarp = (blockIdx.x * blockDim.x + threadIdx.x) >> 5;
    int lane  = threadIdx.x & 31;
    if (gwarp >= T_TOK) return;
    const float* xr = x + (size_t)gwarp * D_DIM;

    float xv[24];
#pragma unroll
    for (int i = 0; i < 24; i++) xv[i] = xr[i * 32 + lane];

    float lg[8];
#pragma unroll
    for (int e = 0; e < 8; e++) {
        const float* w = gw + e * D_DIM;
        float s = 0.0f;
#pragma unroll
        for (int i = 0; i < 24; i++) s += xv[i] * w[i * 32 + lane];
#pragma unroll
        for (int o = 16; o > 0; o >>= 1) s += __shfl_xor_sync(0xffffffffu, s, o);
        lg[e] = s;
    }

    if (lane == 0) {
        float b1 = -1e30f, b2 = -1e30f; int i1 = 0, i2 = 0;
#pragma unroll
        for (int e = 0; e < 8; e++) {
            float b = lg[e] + bias[e];
            if (b > b1)      { b2 = b1; i2 = i1; b1 = b; i1 = e; }
            else if (b > b2) { b2 = b;  i2 = e; }
        }
        float l1 = lg[i1], l2 = lg[i2];
        float m = fmaxf(l1, l2);
        float e1 = expf(l1 - m), e2 = expf(l2 - m);
        float inv = 1.0f / (e1 + e2);
        float w1 = e1 * inv, w2 = e2 * inv;

        float mm = lg[0];
#pragma unroll
        for (int e = 1; e < 8; e++) mm = fmaxf(mm, lg[e]);
        float s = 0.0f;
#pragma unroll
        for (int e = 0; e < 8; e++) s += expf(lg[e] - mm);
        float lse = mm + logf(s);
        atomicAdd(&g_z_acc, lse * lse);

        int p1 = atomicAdd(&g_cnt[i1], 1);
        g_tok[i1 * T_TOK + p1] = gwarp;
        g_slot[2 * gwarp + 0] = i1 * T_TOK + p1;
        g_wt  [2 * gwarp + 0] = w1;
        int p2 = atomicAdd(&g_cnt[i2], 1);
        g_tok[i2 * T_TOK + p2] = gwarp;
        g_slot[2 * gwarp + 1] = i2 * T_TOK + p2;
        g_wt  [2 * gwarp + 1] = w2;
    }
}

// smem layout constants (in halves)
#define G1_A_ST   (128 * 40)
#define G1_B_ST   (32 * 72)
#define G1_STAGES 4
#define G1_SMEM   ((G1_A_ST + 2 * G1_B_ST) * G1_STAGES * 2)   // 77824 B

#define G2_A_ST   (128 * 40)
#define G2_B_ST   (32 * 136)
#define G2_STAGES 3
#define G2_SMEM   ((G2_A_ST + G2_B_ST) * G2_STAGES * 2)       // 56832 B

// ---------------- kernel 2: fp16 GEMM1, 128x64 tile, BK=32, 4-stage, 1 sync/step ----------------
__global__ void __launch_bounds__(256, 2) k_gemm1() {
    extern __shared__ __align__(16) char dynsm[];
    const int e   = blockIdx.z;
    const int cnt = g_cnt[e];
    const int m0  = blockIdx.x * 128;
    if (m0 >= cnt) return;
    const int n0  = blockIdx.y * 64;

    __half* sA  = (__half*)dynsm;                       // [4][128][40]
    __half* sBg = sA + G1_STAGES * G1_A_ST;             // [4][32][72]
    __half* sBu = sBg + G1_STAGES * G1_B_ST;            // [4][32][72]

    const int tid  = threadIdx.x;
    const int warp = tid >> 5;
    const int wm   = warp >> 1;   // 0..3 -> 32-row slab
    const int wn   = warp & 1;    // 0..1 -> 32-col slab

    // A staging: 128 rows x 32 halves -> 512 x 16B chunks, 2/thread
    const __half* a_src[2];
    uint32_t a_dst[2];
#pragma unroll
    for (int q = 0; q < 2; q++) {
        int ch = q * 256 + tid;
        int r = ch >> 2, c = (ch & 3) * 8;
        int row = m0 + r;
        int tok = g_tok[e * T_TOK + (row < cnt ? row : cnt - 1)];
        a_src[q] = g_xh + (size_t)tok * D_DIM + c;
        a_dst[q] = smem_u32(sA + r * 40 + c);
    }
    // B staging: 32 rows x 64 halves -> 256 chunks, 1/thread per matrix
    const int b_r = tid >> 3, b_c = (tid & 7) * 8;
    const size_t wb = (size_t)e * D_DIM * H_DIM;
    const __half* bg_src = g_wgh + wb + (size_t)b_r * H_DIM + n0 + b_c;
    const __half* bu_src = g_wuh + wb + (size_t)b_r * H_DIM + n0 + b_c;
    const uint32_t bg_dst = smem_u32(sBg + b_r * 72 + b_c);
    const uint32_t bu_dst = smem_u32(sBu + b_r * 72 + b_c);

    wmma::fragment<wmma::accumulator, 16, 16, 16, float> accg[2][2], accu[2][2];
#pragma unroll
    for (int i = 0; i < 2; i++)
#pragma unroll
        for (int j = 0; j < 2; j++) {
            wmma::fill_fragment(accg[i][j], 0.0f);
            wmma::fill_fragment(accu[i][j], 0.0f);
        }

    auto issue = [&](int s, int kt) {
        const int k0 = kt * BK;
        const uint32_t aOfs = s * (G1_A_ST * 2);
        const uint32_t bOfs = s * (G1_B_ST * 2);
#pragma unroll
        for (int q = 0; q < 2; q++)
            cpa16(a_dst[q] + aOfs, a_src[q] + k0);
        const size_t o = (size_t)k0 * H_DIM;
        cpa16(bg_dst + bOfs, bg_src + o);
        cpa16(bu_dst + bOfs, bu_src + o);
    };

    const int NK = D_DIM / BK;   // 24
    issue(0, 0); CP_COMMIT();
    issue(1, 1); CP_COMMIT();
    issue(2, 2); CP_COMMIT();

    for (int kt = 0; kt < NK; kt++) {
        const int cur = kt & 3;
        CP_WAIT2();
        __syncthreads();
        if (kt + 3 < NK) issue((kt + 3) & 3, kt + 3);
        CP_COMMIT();
        const __half* cA  = sA  + cur * G1_A_ST;
        const __half* cBg = sBg + cur * G1_B_ST;
        const __half* cBu = sBu + cur * G1_B_ST;
#pragma unroll
        for (int kk = 0; kk < 2; kk++) {
            wmma::fragment<wmma::matrix_a, 16, 16, 16, __half, wmma::row_major> af[2];
            wmma::fragment<wmma::matrix_b, 16, 16, 16, __half, wmma::row_major> bgf[2], buf2[2];
#pragma unroll
            for (int i = 0; i < 2; i++)
                wmma::load_matrix_sync(af[i], cA + (wm * 32 + i * 16) * 40 + kk * 16, 40);
#pragma unroll
            for (int j = 0; j < 2; j++) {
                wmma::load_matrix_sync(bgf[j],  cBg + (kk * 16) * 72 + wn * 32 + j * 16, 72);
                wmma::load_matrix_sync(buf2[j], cBu + (kk * 16) * 72 + wn * 32 + j * 16, 72);
            }
#pragma unroll
            for (int i = 0; i < 2; i++)
#pragma unroll
                for (int j = 0; j < 2; j++) {
                    wmma::mma_sync(accg[i][j], af[i], bgf[j],  accg[i][j]);
                    wmma::mma_sync(accu[i][j], af[i], buf2[j], accu[i][j]);
                }
        }
    }

    // epilogue: act = (g*u)/(1+exp(-g)) with fast intrinsics (MUFU.EX2 + MUFU.RCP),
    // staged via dynsm as float C[128][68]
    __syncthreads();
    float* C = (float*)dynsm;
#pragma unroll
    for (int i = 0; i < 2; i++)
#pragma unroll
        for (int j = 0; j < 2; j++) {
#pragma unroll
            for (int t = 0; t < accg[i][j].num_elements; t++) {
                float g = accg[i][j].x[t];
                float u = accu[i][j].x[t];
                accg[i][j].x[t] = __fdividef(g * u, 1.0f + __expf(-g));
            }
            wmma::store_matrix_sync(C + (wm * 32 + i * 16) * 68 + wn * 32 + j * 16,
                                    accg[i][j], 68, wmma::mem_row_major);
        }
    __syncthreads();
    // 128x64 elems -> half2: 4096 pairs, 16/thread (junk rows in-bounds, never read)
    for (int idx = tid; idx < 128 * 32; idx += 256) {
        int r = idx >> 5, c2 = (idx & 31) * 2;
        __half2 h = __floats2half2_rn(C[r * 68 + c2], C[r * 68 + c2 + 1]);
        *(__half2*)(g_acth + ((size_t)e * T_TOK + m0 + r) * H_DIM + n0 + c2) = h;
    }
}

// ---------------- kernel 3: fp16 GEMM2, 128x128 tile, BK=32, 3-stage, 1 sync/step ----------------
__global__ void __launch_bounds__(256, 2) k_gemm2() {
    extern __shared__ __align__(16) char dynsm[];
    const int e   = blockIdx.z;
    const int cnt = g_cnt[e];
    const int m0  = blockIdx.y * 128;
    if (m0 >= cnt) return;
    const int n0  = blockIdx.x * 128;

    __half* sA = (__half*)dynsm;               // [3][128][40]
    __half* sB = sA + G2_STAGES * G2_A_ST;     // [3][32][136]

    const int tid  = threadIdx.x;
    const int warp = tid >> 5;
    const int wm   = warp >> 1;   // 0..3 -> 32-row slab
    const int wn   = warp & 1;    // 0..1 -> 64-col slab

    // A: 512 chunks, 2/thread (fp16 act, dense slot rows)
    const __half* a_src[2];
    uint32_t a_dst[2];
#pragma unroll
    for (int q = 0; q < 2; q++) {
        int ch = q * 256 + tid;
        int r = ch >> 2, c = (ch & 3) * 8;
        a_src[q] = g_acth + ((size_t)e * T_TOK + m0 + r) * H_DIM + c;
        a_dst[q] = smem_u32(sA + r * 40 + c);
    }
    // B: 32 rows x 128 halves -> 512 chunks, 2/thread
    const __half* b_src[2];
    uint32_t b_dst[2];
    const size_t wb = (size_t)e * H_DIM * D_DIM;
#pragma unroll
    for (int q = 0; q < 2; q++) {
        int ch = q * 256 + tid;
        int r = ch >> 4, c = (ch & 15) * 8;
        b_src[q] = g_wdh + wb + (size_t)r * D_DIM + n0 + c;
        b_dst[q] = smem_u32(sB + r * 136 + c);
    }

    wmma::fragment<wmma::accumulator, 16, 16, 16, float> acc[2][4];
#pragma unroll
    for (int i = 0; i < 2; i++)
#pragma unroll
        for (int j = 0; j < 4; j++) wmma::fill_fragment(acc[i][j], 0.0f);

    auto issue = [&](int s, int kt) {
        const int k0 = kt * BK;
        const uint32_t aOfs = s * (G2_A_ST * 2);
        const uint32_t bOfs = s * (G2_B_ST * 2);
#pragma unroll
        for (int q = 0; q < 2; q++)
            cpa16(a_dst[q] + aOfs, a_src[q] + k0);
#pragma unroll
        for (int q = 0; q < 2; q++)
            cpa16(b_dst[q] + bOfs, b_src[q] + (size_t)k0 * D_DIM);
    };

    const int NK = H_DIM / BK;   // 84
    issue(0, 0); CP_COMMIT();
    issue(1, 1); CP_COMMIT();

    int cur = 0;
    for (int kt = 0; kt < NK; kt++) {
        CP_WAIT1();
        __syncthreads();
        if (kt + 2 < NK) issue((cur + 2) % 3, kt + 2);
        CP_COMMIT();
        const __half* cA = sA + cur * G2_A_ST;
        const __half* cB = sB + cur * G2_B_ST;
#pragma unroll
        for (int kk = 0; kk < 2; kk++) {
            wmma::fragment<wmma::matrix_a, 16, 16, 16, __half, wmma::row_major> af[2];
            wmma::fragment<wmma::matrix_b, 16, 16, 16, __half, wmma::row_major> bf[4];
#pragma unroll
            for (int i = 0; i < 2; i++)
                wmma::load_matrix_sync(af[i], cA + (wm * 32 + i * 16) * 40 + kk * 16, 40);
#pragma unroll
            for (int j = 0; j < 4; j++)
                wmma::load_matrix_sync(bf[j], cB + (kk * 16) * 136 + wn * 64 + j * 16, 136);
#pragma unroll
            for (int i = 0; i < 2; i++)
#pragma unroll
                for (int j = 0; j < 4; j++)
                    wmma::mma_sync(acc[i][j], af[i], bf[j], acc[i][j]);
        }
        cur = (cur + 1) % 3;
    }

    // epilogue: per-slot fp32 result direct to g_y (no atomics; junk rows never combined)
    float* ybase = g_y + ((size_t)e * T_TOK + m0) * D_DIM + n0;
#pragma unroll
    for (int i = 0; i < 2; i++)
#pragma unroll
        for (int j = 0; j < 4; j++)
            wmma::store_matrix_sync(ybase + (size_t)(wm * 32 + i * 16) * D_DIM + wn * 64 + j * 16,
                                    acc[i][j], D_DIM, wmma::mem_row_major);
}

// ---------------- kernel 4: combine two expert slots per token ----------------
__global__ void k_combine(float* __restrict__ out) {
    const int t = blockIdx.x;
    const int s0 = g_slot[2 * t], s1 = g_slot[2 * t + 1];
    const float w0 = g_wt[2 * t], w1 = g_wt[2 * t + 1];
    const float4* y0 = (const float4*)(g_y + (size_t)s0 * D_DIM);
    const float4* y1 = (const float4*)(g_y + (size_t)s1 * D_DIM);
    float4 a = y0[threadIdx.x];
    float4 b = y1[threadIdx.x];
    float4 r;
    r.x = w0 * a.x + w1 * b.x;
    r.y = w0 * a.y + w1 * b.y;
    r.z = w0 * a.z + w1 * b.z;
    r.w = w0 * a.w + w1 * b.w;
    ((float4*)(out + (size_t)t * D_DIM))[threadIdx.x] = r;
}

// ---------------- kernel 5: finalize z-loss ----------------
__global__ void k_final(float* __restrict__ out, int out_size) {
    if (out_size > T_TOK * D_DIM)
        out[T_TOK * D_DIM] = 1e-5f * g_z_acc / (float)T_TOK;
}

// ---------------- launcher ----------------
extern "C" void kernel_launch(void* const* d_in, const int* in_sizes, int n_in,
                              void* d_out, int out_size) {
    const float* x     = (const float*)d_in[0];  // [2,2048,768]
    const float* gw    = (const float*)d_in[1];  // [8,768]
    const float* bias  = (const float*)d_in[2];  // [8]
    const float* wgate = (const float*)d_in[3];  // [8,768,2688]
    const float* wup   = (const float*)d_in[4];  // [8,768,2688]
    const float* wdown = (const float*)d_in[5];  // [8,2688,768]
    float* out = (float*)d_out;

    static bool attr_set = false;
    if (!attr_set) {
        cudaFuncSetAttribute(k_gemm1, cudaFuncAttributeMaxDynamicSharedMemorySize, G1_SMEM);
        cudaFuncSetAttribute(k_gemm2, cudaFuncAttributeMaxDynamicSharedMemorySize, G2_SMEM);
        attr_set = true;
    }

    k_init<<<1, 32>>>();
    k_cvt<<<2048, 256>>>(x, wgate, wup, wdown);
    k_router<<<T_TOK / 8, 256>>>(x, gw, bias);

    dim3 g1(T_TOK / 128, H_DIM / 64, E_NUM);   // 32 x 42 x 8 (M fastest -> weight-slab L2 reuse)
    k_gemm1<<<g1, 256, G1_SMEM>>>();

    dim3 g2(D_DIM / 128, T_TOK / 128, E_NUM);  // 6 x 32 x 8 (N fastest -> A-slab L2 reuse)
    k_gemm2<<<g2, 256, G2_SMEM>>>();

    k_combine<<<T_TOK, 192>>>(out);
    k_final<<<1, 1>>>(out, out_size);
}